// round 2
// baseline (speedup 1.0000x reference)
#include <cuda_runtime.h>
#include <stdint.h>

#define NN 50000
#define NE 800000
#define IN_DIM 96
#define HID 32
#define OUT_DIM 64

// ---------------- scratch (device globals; no allocation allowed) ----------
__device__ __align__(16) float g_y1[NN * HID];    // x @ W1l   (to be aggregated)
__device__ __align__(16) float g_z1[NN * HID];    // x @ W1r   (self term)
__device__ __align__(16) float g_agg1[NN * HID];  // scatter accum, layer 1
__device__ __align__(16) float g_h[NN * HID];     // hidden activations
__device__ __align__(16) float g_agg2[NN * HID];  // scatter accum, layer 2
__device__ float g_cnt[NN];
__device__ float g_invc[NN];

// ---------------- zero the accumulators (needed every call) ----------------
__global__ void zero_bufs() {
    int i = blockIdx.x * blockDim.x + threadIdx.x;
    const int nv4 = NN * HID / 4;
    if (i < nv4) {
        ((float4*)g_agg1)[i] = make_float4(0.f, 0.f, 0.f, 0.f);
        ((float4*)g_agg2)[i] = make_float4(0.f, 0.f, 0.f, 0.f);
    }
    if (i < NN) g_cnt[i] = 0.f;
}

// ---------------- layer-1 GEMM: [y1 | z1] = x @ [W1l | W1r] ----------------
// thread-per-node, 64 fp32 accumulators, weights broadcast from smem.
__global__ void __launch_bounds__(128) gemm1_kernel(
    const float* __restrict__ x,
    const float* __restrict__ W1l,
    const float* __restrict__ W1r,
    int n)
{
    __shared__ float sW[IN_DIM][2 * HID];  // [96][64] = 24 KB
    for (int i = threadIdx.x; i < IN_DIM * HID; i += blockDim.x) {
        int k = i / HID, j = i % HID;
        sW[k][j]       = W1l[i];
        sW[k][j + HID] = W1r[i];
    }
    __syncthreads();

    int node = blockIdx.x * blockDim.x + threadIdx.x;
    if (node >= n) return;

    float acc[64];
#pragma unroll
    for (int j = 0; j < 64; j++) acc[j] = 0.f;

    const float4* xr = (const float4*)(x + (size_t)node * IN_DIM);
#pragma unroll 1
    for (int kq = 0; kq < IN_DIM / 4; kq++) {
        float4 xv = __ldg(&xr[kq]);
        float xs[4] = {xv.x, xv.y, xv.z, xv.w};
#pragma unroll
        for (int kk = 0; kk < 4; kk++) {
            float xk = xs[kk];
            const float* wr = sW[kq * 4 + kk];
#pragma unroll
            for (int j = 0; j < 64; j += 4) {
                float4 w = *(const float4*)&wr[j];
                acc[j + 0] += xk * w.x;
                acc[j + 1] += xk * w.y;
                acc[j + 2] += xk * w.z;
                acc[j + 3] += xk * w.w;
            }
        }
    }

    float* y = g_y1 + (size_t)node * HID;
    float* z = g_z1 + (size_t)node * HID;
#pragma unroll
    for (int j = 0; j < HID; j += 4) {
        *(float4*)&y[j] = make_float4(acc[j], acc[j + 1], acc[j + 2], acc[j + 3]);
        *(float4*)&z[j] = make_float4(acc[HID + j], acc[HID + j + 1],
                                      acc[HID + j + 2], acc[HID + j + 3]);
    }
}

// ---------------- edge scatter: agg[dst] += feat[src] (dim 32) -------------
// 8 threads per edge, one float4 each -> one 128B line gather + v4 red.
// edge_index is int32 (JAX x64 disabled downgrades int64 -> int32).
__global__ void __launch_bounds__(256) scatter_kernel(
    const int* __restrict__ ei, int E, int layer)
{
    int tid = blockIdx.x * blockDim.x + threadIdx.x;
    int e = tid >> 3;
    int l = tid & 7;
    if (e >= E) return;

    int src = ei[e];
    int dst = ei[E + e];

    const float* feat = (layer == 0) ? g_y1 : g_h;
    float*       agg  = (layer == 0) ? g_agg1 : g_agg2;

    float4 v = *(const float4*)(feat + (size_t)src * HID + l * 4);
    float* p = agg + (size_t)dst * HID + l * 4;
    asm volatile("red.global.add.v4.f32 [%0], {%1,%2,%3,%4};"
                 :: "l"(p), "f"(v.x), "f"(v.y), "f"(v.z), "f"(v.w)
                 : "memory");
    if (layer == 0 && l == 0) atomicAdd(g_cnt + dst, 1.0f);
}

// ---------------- combine layer 1: h = relu(agg1/cnt + z1 + b1) ------------
__global__ void combine1_kernel(const float* __restrict__ b1, int n) {
    int tid = blockIdx.x * blockDim.x + threadIdx.x;
    int node = tid >> 3;
    int q = tid & 7;
    if (node >= n) return;

    float c = g_cnt[node];
    float invc = 1.0f / fmaxf(c, 1.0f);
    if (q == 0) g_invc[node] = invc;

    size_t off = (size_t)node * HID + q * 4;
    float4 a  = *(const float4*)&g_agg1[off];
    float4 z  = *(const float4*)&g_z1[off];
    float4 bb = *(const float4*)&b1[q * 4];
    float4 h;
    h.x = fmaxf(fmaf(a.x, invc, z.x + bb.x), 0.f);
    h.y = fmaxf(fmaf(a.y, invc, z.y + bb.y), 0.f);
    h.z = fmaxf(fmaf(a.z, invc, z.z + bb.z), 0.f);
    h.w = fmaxf(fmaf(a.w, invc, z.w + bb.w), 0.f);
    *(float4*)&g_h[off] = h;
}

// ---------------- layer 2: out = (agg2/cnt)@W2l + h@W2r + b2 ---------------
// thread-per-node GEMV on concat(agg2*invc, h) with stacked 64x64 weights.
__global__ void __launch_bounds__(128) layer2_kernel(
    const float* __restrict__ W2l,
    const float* __restrict__ W2r,
    const float* __restrict__ b2,
    float* __restrict__ out,
    int n)
{
    __shared__ float sW[2 * HID][OUT_DIM];  // 64x64 = 16 KB; rows 0..31 = W2l
    for (int i = threadIdx.x; i < HID * OUT_DIM; i += blockDim.x) {
        int k = i / OUT_DIM, j = i % OUT_DIM;
        sW[k][j]       = W2l[i];
        sW[k + HID][j] = W2r[i];
    }
    __syncthreads();

    int node = blockIdx.x * blockDim.x + threadIdx.x;
    if (node >= n) return;

    float invc = g_invc[node];
    float v[64];
#pragma unroll
    for (int k = 0; k < HID; k += 4) {
        float4 a = *(const float4*)&g_agg2[(size_t)node * HID + k];
        v[k + 0] = a.x * invc;
        v[k + 1] = a.y * invc;
        v[k + 2] = a.z * invc;
        v[k + 3] = a.w * invc;
        float4 hh = *(const float4*)&g_h[(size_t)node * HID + k];
        v[HID + k + 0] = hh.x;
        v[HID + k + 1] = hh.y;
        v[HID + k + 2] = hh.z;
        v[HID + k + 3] = hh.w;
    }

#pragma unroll 1
    for (int j = 0; j < OUT_DIM; j += 4) {
        float4 bb = *(const float4*)&b2[j];
        float a0 = bb.x, a1 = bb.y, a2 = bb.z, a3 = bb.w;
#pragma unroll
        for (int k = 0; k < 64; k++) {
            float4 w = *(const float4*)&sW[k][j];
            a0 += v[k] * w.x;
            a1 += v[k] * w.y;
            a2 += v[k] * w.z;
            a3 += v[k] * w.w;
        }
        *(float4*)&out[(size_t)node * OUT_DIM + j] = make_float4(a0, a1, a2, a3);
    }
}

// ---------------- launch --------------------------------------------------
extern "C" void kernel_launch(void* const* d_in, const int* in_sizes, int n_in,
                              void* d_out, int out_size)
{
    const float* x   = (const float*)d_in[0];
    const int*   ei  = (const int*)d_in[1];
    const float* W1l = (const float*)d_in[2];
    const float* W1r = (const float*)d_in[3];
    const float* b1  = (const float*)d_in[4];
    const float* W2l = (const float*)d_in[5];
    const float* W2r = (const float*)d_in[6];
    const float* b2  = (const float*)d_in[7];
    float*       out = (float*)d_out;

    int n = in_sizes[0] / IN_DIM;   // 50000
    int E = in_sizes[1] / 2;        // 800000

    // 1) zero accumulators + counts
    {
        int tot = NN * HID / 4;  // covers agg1/agg2 float4s and cnt
        zero_bufs<<<(tot + 255) / 256, 256>>>();
    }
    // 2) fused layer-1 GEMM: y1 = x@W1l, z1 = x@W1r
    gemm1_kernel<<<(n + 127) / 128, 128>>>(x, W1l, W1r, n);
    // 3) scatter y1 into agg1 (+ degree counts)
    {
        long long work = (long long)E * 8;
        scatter_kernel<<<(int)((work + 255) / 256), 256>>>(ei, E, 0);
    }
    // 4) h = relu(agg1/cnt + z1 + b1)
    combine1_kernel<<<(n * 8 + 255) / 256, 256>>>(b1, n);
    // 5) scatter h into agg2
    {
        long long work = (long long)E * 8;
        scatter_kernel<<<(int)((work + 255) / 256), 256>>>(ei, E, 1);
    }
    // 6) out = (agg2/cnt)@W2l + h@W2r + b2
    layer2_kernel<<<(n + 127) / 128, 128>>>(W2l, W2r, b2, out, n);
}